// round 1
// baseline (speedup 1.0000x reference)
#include <cuda_runtime.h>

#define NN 65536
#define EE 524288
#define BBG 256
#define FEAT 64
#define EMB 128
#define NHD 4
#define OUTD 32

// ---------------- scratch (static device globals; no allocation) ----------------
__device__ float g_aggf[NN * FEAT];        // conv0 max-aggregation result
__device__ float g_buf[NN * EMB];          // h / "new" buffer (pre-BN)
__device__ float g_cur[NN * EMB];          // current node features
__device__ float g_score[NHD * NN];
__device__ float g_sm[NHD * NN];
__device__ float g_gate[NHD * NN];
__device__ float g_att[NHD * NN];
__device__ unsigned char g_mask[NN];       // packed keep bits (4 heads)
__device__ float g_part[2 * 256 * EMB];    // BN partial sums
__device__ float g_meanvar[2 * EMB];       // mean, inv-std
__device__ float g_pooled[NHD * BBG * EMB];
__device__ float g_logits[BBG * NHD];
__device__ int g_deg[NN];
__device__ int g_rp[NN + 1];
__device__ int g_cursor[NN];
__device__ int g_csrc[EE];
__device__ int g_bsum[256];
__device__ int g_boff[256];

__device__ __forceinline__ float lrelu(float v) { return v > 0.f ? v : 0.01f * v; }

// ---------------- CSR build (by dst) ----------------
__global__ void k_zero_deg() {
    int i = blockIdx.x * blockDim.x + threadIdx.x;
    if (i < NN) g_deg[i] = 0;
}

__global__ void k_hist(const int* __restrict__ dst) {
    int e = blockIdx.x * blockDim.x + threadIdx.x;
    if (e < EE) atomicAdd(&g_deg[dst[e]], 1);
}

__global__ void k_scan1() {
    int b = blockIdx.x, t = threadIdx.x;
    int v = g_deg[b * 256 + t];
    __shared__ int a[256];
    a[t] = v;
    __syncthreads();
    for (int off = 1; off < 256; off <<= 1) {
        int x = (t >= off) ? a[t - off] : 0;
        __syncthreads();
        a[t] += x;
        __syncthreads();
    }
    g_rp[b * 256 + t] = a[t] - v;              // exclusive within block
    if (t == 255) g_bsum[b] = a[t];
}

__global__ void k_scan2() {
    int t = threadIdx.x;
    int v = g_bsum[t];
    __shared__ int a[256];
    a[t] = v;
    __syncthreads();
    for (int off = 1; off < 256; off <<= 1) {
        int x = (t >= off) ? a[t - off] : 0;
        __syncthreads();
        a[t] += x;
        __syncthreads();
    }
    g_boff[t] = a[t] - v;                      // exclusive block offsets
}

__global__ void k_scan3() {
    int i = blockIdx.x * blockDim.x + threadIdx.x;
    if (i < NN) {
        int r = g_rp[i] + g_boff[i >> 8];
        g_rp[i] = r;
        g_cursor[i] = r;
        if (i == 0) g_rp[NN] = EE;
    }
}

__global__ void k_scatter(const int* __restrict__ src, const int* __restrict__ dst) {
    int e = blockIdx.x * blockDim.x + threadIdx.x;
    if (e < EE) {
        int p = atomicAdd(&g_cursor[dst[e]], 1);
        g_csrc[p] = src[e];
    }
}

// ---------------- conv0: max aggregation over all edges ----------------
__global__ void k_agg0(const float* __restrict__ x) {
    int wi = (blockIdx.x * blockDim.x + threadIdx.x) >> 5;
    if (wi >= NN) return;
    int lane = threadIdx.x & 31;
    int beg = g_rp[wi], end = g_rp[wi + 1];
    float m0 = -3.4e38f, m1 = -3.4e38f;
    for (int e = beg; e < end; e++) {
        int s = g_csrc[e];
        m0 = fmaxf(m0, x[s * FEAT + lane]);
        m1 = fmaxf(m1, x[s * FEAT + 32 + lane]);
    }
    if (beg == end) { m0 = 0.f; m1 = 0.f; }    // no in-edges -> 0
    g_aggf[wi * FEAT + lane] = m0;
    g_aggf[wi * FEAT + 32 + lane] = m1;
}

// ---------------- conv0 GEMM: g_buf = lrelu(agg@Wrel^T + x@Wroot^T + b0) ----------------
// block = 256 threads, 32 nodes per block, register tile 4 nodes x 4 outs
__global__ void k_conv0(const float* __restrict__ x, const float* __restrict__ wrel,
                        const float* __restrict__ wroot, const float* __restrict__ b0) {
    __shared__ float sW[64 * 132];   // [k][j], pitch 132 (16B aligned)
    __shared__ float sIn[64 * 36];   // [k][n], pitch 36
    int tx = threadIdx.x;
    int og = tx & 31;                // out group: j = og*4 + q
    int ng = tx >> 5;                // node group: n = ng*4 + p
    int nbase = blockIdx.x * 32;

    float acc[4][4];
#pragma unroll
    for (int p = 0; p < 4; p++)
#pragma unroll
        for (int q = 0; q < 4; q++) acc[p][q] = 0.f;

    for (int c = 0; c < 2; c++) {
        const float* W = c ? wroot : wrel;
        const float* In = c ? x : g_aggf;
#pragma unroll
        for (int r = 0; r < 32; r++) {
            int lin = r * 256 + tx;
            int j = lin >> 6, k = lin & 63;
            sW[k * 132 + j] = W[j * 64 + k];
        }
#pragma unroll
        for (int r = 0; r < 8; r++) {
            int lin = r * 256 + tx;
            int n = lin >> 6, k = lin & 63;
            sIn[k * 36 + n] = In[(nbase + n) * 64 + k];
        }
        __syncthreads();
#pragma unroll 16
        for (int k = 0; k < 64; k++) {
            float4 wv = *(const float4*)&sW[k * 132 + og * 4];
            float4 iv = *(const float4*)&sIn[k * 36 + ng * 4];
            acc[0][0] += iv.x * wv.x; acc[0][1] += iv.x * wv.y; acc[0][2] += iv.x * wv.z; acc[0][3] += iv.x * wv.w;
            acc[1][0] += iv.y * wv.x; acc[1][1] += iv.y * wv.y; acc[1][2] += iv.y * wv.z; acc[1][3] += iv.y * wv.w;
            acc[2][0] += iv.z * wv.x; acc[2][1] += iv.z * wv.y; acc[2][2] += iv.z * wv.z; acc[2][3] += iv.z * wv.w;
            acc[3][0] += iv.w * wv.x; acc[3][1] += iv.w * wv.y; acc[3][2] += iv.w * wv.z; acc[3][3] += iv.w * wv.w;
        }
        __syncthreads();
    }
    int j0 = og * 4;
    float4 bb = *(const float4*)&b0[j0];
#pragma unroll
    for (int p = 0; p < 4; p++) {
        int node = nbase + ng * 4 + p;
        float4 o;
        o.x = lrelu(acc[p][0] + bb.x);
        o.y = lrelu(acc[p][1] + bb.y);
        o.z = lrelu(acc[p][2] + bb.z);
        o.w = lrelu(acc[p][3] + bb.w);
        *(float4*)&g_buf[node * EMB + j0] = o;
    }
}

// ---------------- BN stats over g_buf (deterministic 2-stage) ----------------
__global__ void k_stats1() {
    int b = blockIdx.x, t = threadIdx.x;   // 256 blocks x 128 threads
    const float* p = g_buf + (size_t)b * 256 * EMB;
    float s = 0.f, ss = 0.f;
    for (int r = 0; r < 256; r++) {
        float v = p[r * EMB + t];
        s += v;
        ss += v * v;
    }
    g_part[b * EMB + t] = s;
    g_part[256 * EMB + b * EMB + t] = ss;
}

__global__ void k_stats2() {
    int t = threadIdx.x;  // 128
    float s = 0.f, ss = 0.f;
    for (int b = 0; b < 256; b++) {
        s += g_part[b * EMB + t];
        ss += g_part[256 * EMB + b * EMB + t];
    }
    float mean = s * (1.f / NN);
    float var = ss * (1.f / NN) - mean * mean;
    g_meanvar[t] = mean;
    g_meanvar[EMB + t] = 1.f / sqrtf(var + 1e-5f);
}

__global__ void k_bn0(const float* __restrict__ gam, const float* __restrict__ bet) {
    int stride = gridDim.x * blockDim.x;
    for (int idx = blockIdx.x * blockDim.x + threadIdx.x; idx < NN * EMB; idx += stride) {
        int f = idx & (EMB - 1);
        g_cur[idx] = gam[f] * (g_buf[idx] - g_meanvar[f]) * g_meanvar[EMB + f] + bet[f];
    }
}

__global__ void k_update(const float* __restrict__ gam, const float* __restrict__ bet) {
    int stride = gridDim.x * blockDim.x;
    for (int idx = blockIdx.x * blockDim.x + threadIdx.x; idx < NN * EMB; idx += stride) {
        int f = idx & (EMB - 1);
        float bn = gam[f] * (g_buf[idx] - g_meanvar[f]) * g_meanvar[EMB + f] + bet[f];
        g_cur[idx] = 0.5f * g_cur[idx] + 0.25f * bn;
    }
}

__global__ void k_zero_buf() {
    int stride = gridDim.x * blockDim.x;
    for (int idx = blockIdx.x * blockDim.x + threadIdx.x; idx < NN * EMB; idx += stride)
        g_buf[idx] = 0.f;
}

// ---------------- pooling scores: score[h][i] = cur[i] . w[h] (warp per node) ----------------
__global__ void k_scores(const float* __restrict__ w4) {
    int wi = (blockIdx.x * blockDim.x + threadIdx.x) >> 5;
    if (wi >= NN) return;
    int lane = threadIdx.x & 31;
    float c0 = g_cur[wi * EMB + lane];
    float c1 = g_cur[wi * EMB + 32 + lane];
    float c2 = g_cur[wi * EMB + 64 + lane];
    float c3 = g_cur[wi * EMB + 96 + lane];
#pragma unroll
    for (int h = 0; h < NHD; h++) {
        const float* w = w4 + h * EMB;
        float a = c0 * w[lane] + c1 * w[32 + lane] + c2 * w[64 + lane] + c3 * w[96 + lane];
#pragma unroll
        for (int o = 16; o; o >>= 1) a += __shfl_xor_sync(0xffffffffu, a, o);
        if (lane == 0) g_score[h * NN + wi] = a;
    }
}

// ---------------- per-graph softmax + keep decision (4 heads) ----------------
__global__ void k_softkeep(float min_score) {
    int g = blockIdx.x, t = threadIdx.x;
    int i = g * 256 + t;
    __shared__ float red[256];
    unsigned mb = 0;
    for (int h = 0; h < NHD; h++) {
        float v = g_score[h * NN + i];
        red[t] = v;
        __syncthreads();
        for (int o = 128; o > 0; o >>= 1) {
            if (t < o) red[t] = fmaxf(red[t], red[t + o]);
            __syncthreads();
        }
        float m = red[0];
        __syncthreads();
        float e = expf(v - m);
        red[t] = e;
        __syncthreads();
        for (int o = 128; o > 0; o >>= 1) {
            if (t < o) red[t] += red[t + o];
            __syncthreads();
        }
        float s = red[0];
        __syncthreads();
        float sm = e / (s + 1e-16f);
        float smax = 1.0f / (s + 1e-16f);   // argmax node has e == 1 exactly
        float thr = fminf(smax - 1e-7f, min_score);
        if (sm > thr) mb |= (1u << h);
        g_sm[h * NN + i] = sm;
    }
    g_mask[i] = (unsigned char)mb;
}

// ---------------- block head conv: per-node, only kept nodes active ----------------
__global__ void k_headout(const float* __restrict__ wrel, const float* __restrict__ wroot,
                          const float* __restrict__ bias) {
    int i = blockIdx.x;
    unsigned mb = g_mask[i];
    if (!mb) return;
    int t = threadIdx.x;   // 128
    __shared__ float sCur[EMB];
    __shared__ float sAgg[NHD][EMB];
    __shared__ float sSm[NHD];
    sCur[t] = g_cur[i * EMB + t];
    if (t < NHD) sSm[t] = g_sm[t * NN + i];
    int beg = g_rp[i], end = g_rp[i + 1];
    for (int h = 0; h < NHD; h++) {
        if (!((mb >> h) & 1)) continue;  // uniform across block
        float m = -3.4e38f;
        bool any = false;
        for (int e = beg; e < end; e++) {
            int s = g_csrc[e];
            if ((g_mask[s] >> h) & 1) {
                m = fmaxf(m, g_cur[s * EMB + t] * g_sm[h * NN + s]);
                any = true;
            }
        }
        sAgg[h][t] = any ? m : 0.f;
    }
    __syncthreads();
    int h = t >> 5, j = t & 31;
    if ((mb >> h) & 1) {
        float smv = sSm[h];
        float acc = bias[h * OUTD + j];
        const float* wr = &wrel[(h * OUTD + j) * EMB];
        const float* wo = &wroot[(h * OUTD + j) * EMB];
#pragma unroll 16
        for (int k = 0; k < EMB; k++)
            acc += wr[k] * sAgg[h][k] + wo[k] * (sCur[k] * smv);
        g_buf[i * EMB + h * OUTD + j] = lrelu(acc);
    }
}

// ---------------- classifier gate MLP at kept nodes ----------------
__global__ void k_gate(const float* __restrict__ gW1, const float* __restrict__ gb1,
                       const float* __restrict__ gW2, const float* __restrict__ gb2) {
    int i = blockIdx.x;
    unsigned mb = g_mask[i];
    if (!mb) return;
    int t = threadIdx.x;   // 128
    __shared__ float sCur[EMB];
    __shared__ float red[EMB];
    sCur[t] = g_cur[i * EMB + t];
    __syncthreads();
    for (int c = 0; c < NHD; c++) {
        if (!((mb >> c) & 1)) continue;  // uniform
        float smv = g_sm[c * NN + i];
        float acc = gb1[c * EMB + t];
        const float* w = &gW1[(c * EMB + t) * EMB];
#pragma unroll 16
        for (int k = 0; k < EMB; k++) acc += w[k] * (sCur[k] * smv);
        acc = lrelu(acc);
        red[t] = acc * gW2[c * EMB + t];
        __syncthreads();
        for (int o = 64; o > 0; o >>= 1) {
            if (t < o) red[t] += red[t + o];
            __syncthreads();
        }
        if (t == 0) g_gate[c * NN + i] = red[0] + gb2[c];
        __syncthreads();
    }
}

// ---------------- per-graph attention softmax over kept nodes ----------------
__global__ void k_att() {
    int g = blockIdx.x, t = threadIdx.x;
    int i = g * 256 + t;
    __shared__ float red[256];
    unsigned mb = g_mask[i];
    for (int c = 0; c < NHD; c++) {
        float z = ((mb >> c) & 1) ? g_gate[c * NN + i] : __int_as_float(0xff800000);
        red[t] = z;
        __syncthreads();
        for (int o = 128; o > 0; o >>= 1) {
            if (t < o) red[t] = fmaxf(red[t], red[t + o]);
            __syncthreads();
        }
        float m = red[0];
        __syncthreads();
        float e = expf(z - m);   // z = -inf -> 0
        red[t] = e;
        __syncthreads();
        for (int o = 128; o > 0; o >>= 1) {
            if (t < o) red[t] += red[t + o];
            __syncthreads();
        }
        float s = red[0];
        __syncthreads();
        g_att[c * NN + i] = e / (s + 1e-16f);
    }
}

// ---------------- attention-weighted pooling per (graph, head) ----------------
__global__ void k_pooled() {
    int g = blockIdx.x, c = blockIdx.y, t = threadIdx.x;   // 128
    int base = g * 256;
    float acc = 0.f;
    for (int r = 0; r < 256; r++) {
        float a = g_att[c * NN + base + r];
        if (a != 0.f) {
            float smv = g_sm[c * NN + base + r];
            acc += (a * smv) * g_cur[(base + r) * EMB + t];
        }
    }
    g_pooled[(c * BBG + g) * EMB + t] = acc;
}

// ---------------- final MLP per (graph, head) ----------------
__global__ void k_y(const float* __restrict__ fW1, const float* __restrict__ fb1,
                    const float* __restrict__ fW2, const float* __restrict__ fb2) {
    int g = blockIdx.x, c = blockIdx.y, t = threadIdx.x;
    __shared__ float sp[EMB];
    __shared__ float red[EMB];
    sp[t] = g_pooled[(c * BBG + g) * EMB + t];
    __syncthreads();
    float acc = fb1[c * EMB + t];
    const float* w = &fW1[(c * EMB + t) * EMB];
#pragma unroll 16
    for (int k = 0; k < EMB; k++) acc += w[k] * sp[k];
    acc = lrelu(acc);
    red[t] = acc * fW2[c * EMB + t];
    __syncthreads();
    for (int o = 64; o > 0; o >>= 1) {
        if (t < o) red[t] += red[t + o];
        __syncthreads();
    }
    if (t == 0) g_logits[g * NHD + c] = red[0] + fb2[c];
}

__global__ void k_lsm(float* __restrict__ out) {
    int g = blockIdx.x * blockDim.x + threadIdx.x;
    if (g >= BBG) return;
    float l[NHD];
    float m = -3.4e38f;
#pragma unroll
    for (int c = 0; c < NHD; c++) { l[c] = g_logits[g * NHD + c]; m = fmaxf(m, l[c]); }
    float s = 0.f;
#pragma unroll
    for (int c = 0; c < NHD; c++) s += expf(l[c] - m);
    float ls = logf(s);
#pragma unroll
    for (int c = 0; c < NHD; c++) out[g * NHD + c] = l[c] - m - ls;
}

// ---------------- launch ----------------
extern "C" void kernel_launch(void* const* d_in, const int* in_sizes, int n_in,
                              void* d_out, int out_size) {
    const float* x       = (const float*)d_in[0];
    const int*   ei      = (const int*)d_in[1];
    const int*   src     = ei;
    const int*   dst     = ei + EE;
    const float* Wrel0   = (const float*)d_in[3];
    const float* Wroot0  = (const float*)d_in[4];
    const float* b0      = (const float*)d_in[5];
    const float* bn0g    = (const float*)d_in[6];
    const float* bn0b    = (const float*)d_in[7];
    const float* blk_pw  = (const float*)d_in[8];
    const float* blk_Wr  = (const float*)d_in[9];
    const float* blk_Wo  = (const float*)d_in[10];
    const float* blk_bb  = (const float*)d_in[11];
    const float* blk_bng = (const float*)d_in[12];
    const float* blk_bnb = (const float*)d_in[13];
    const float* cls_pw  = (const float*)d_in[14];
    const float* gW1     = (const float*)d_in[15];
    const float* gb1     = (const float*)d_in[16];
    const float* gW2     = (const float*)d_in[17];
    const float* gb2     = (const float*)d_in[18];
    const float* fW1     = (const float*)d_in[19];
    const float* fb1     = (const float*)d_in[20];
    const float* fW2     = (const float*)d_in[21];
    const float* fb2     = (const float*)d_in[22];
    float* out = (float*)d_out;

    // CSR by dst (recomputed every call; fully deterministic row_ptr)
    k_zero_deg<<<256, 256>>>();
    k_hist<<<EE / 256, 256>>>(dst);
    k_scan1<<<256, 256>>>();
    k_scan2<<<1, 256>>>();
    k_scan3<<<256, 256>>>();
    k_scatter<<<EE / 256, 256>>>(src, dst);

    // conv0 -> lrelu -> bn0
    k_agg0<<<NN / 8, 256>>>(x);
    k_conv0<<<NN / 32, 256>>>(x, Wrel0, Wroot0, b0);
    k_stats1<<<256, 128>>>();
    k_stats2<<<1, 128>>>();
    k_bn0<<<2048, 256>>>(bn0g, bn0b);

    // two multi-head blocks
    for (int bi = 0; bi < 2; bi++) {
        k_scores<<<NN / 8, 256>>>(blk_pw + bi * NHD * EMB);
        k_softkeep<<<BBG, 256>>>(0.7f);
        k_zero_buf<<<2048, 256>>>();
        k_headout<<<NN, 128>>>(blk_Wr + bi * NHD * OUTD * EMB,
                               blk_Wo + bi * NHD * OUTD * EMB,
                               blk_bb + bi * NHD * OUTD);
        k_stats1<<<256, 128>>>();
        k_stats2<<<1, 128>>>();
        k_update<<<2048, 256>>>(blk_bng + bi * EMB, blk_bnb + bi * EMB);
    }

    // classifier heads
    k_scores<<<NN / 8, 256>>>(cls_pw);
    k_softkeep<<<BBG, 256>>>(0.8f);
    k_gate<<<NN, 128>>>(gW1, gb1, gW2, gb2);
    k_att<<<BBG, 256>>>();
    dim3 pg(BBG, NHD);
    k_pooled<<<pg, 128>>>();
    k_y<<<pg, 128>>>(fW1, fb1, fW2, fb2);
    k_lsm<<<1, 256>>>(out);
}

// round 4
// speedup vs baseline: 1.3010x; 1.3010x over previous
#include <cuda_runtime.h>

#define NN 65536
#define EE 524288
#define BBG 256
#define FEAT 64
#define EMB 128
#define NHD 4
#define OUTD 32
#define NEG_INF __int_as_float(0xff800000)

// ---------------- scratch (static device globals; no allocation) ----------------
__device__ float g_aggf[NN * FEAT];
__device__ float g_buf[NN * EMB];
__device__ float g_cur[NN * EMB];
__device__ float g_sm[NHD * NN];
__device__ unsigned char g_mask[NN];
__device__ float g_part[2048 * EMB];
__device__ float g_part2[2048 * EMB];
__device__ float g_meanvar[2 * EMB];
__device__ int g_klist[BBG * 256];
__device__ int g_kcnt[BBG];
__device__ int g_deg[NN];
__device__ int g_rp[NN + 1];
__device__ int g_cursor[NN];
__device__ int g_csrc[EE];
__device__ int g_bsum[256];
__device__ int g_boff[256];

__device__ __forceinline__ float lrelu(float v) { return v > 0.f ? v : 0.01f * v; }

// ---------------- CSR build (by dst) ----------------
__global__ void k_zero_deg() {
    int i = blockIdx.x * blockDim.x + threadIdx.x;
    if (i < NN) g_deg[i] = 0;
}
__global__ void k_hist(const int* __restrict__ dst) {
    int e = blockIdx.x * blockDim.x + threadIdx.x;
    if (e < EE) atomicAdd(&g_deg[dst[e]], 1);
}
__global__ void k_scan1() {
    int b = blockIdx.x, t = threadIdx.x;
    int v = g_deg[b * 256 + t];
    __shared__ int a[256];
    a[t] = v; __syncthreads();
    for (int off = 1; off < 256; off <<= 1) {
        int x = (t >= off) ? a[t - off] : 0;
        __syncthreads(); a[t] += x; __syncthreads();
    }
    g_rp[b * 256 + t] = a[t] - v;
    if (t == 255) g_bsum[b] = a[t];
}
__global__ void k_scan2() {
    int t = threadIdx.x;
    int v = g_bsum[t];
    __shared__ int a[256];
    a[t] = v; __syncthreads();
    for (int off = 1; off < 256; off <<= 1) {
        int x = (t >= off) ? a[t - off] : 0;
        __syncthreads(); a[t] += x; __syncthreads();
    }
    g_boff[t] = a[t] - v;
}
__global__ void k_scan3() {
    int i = blockIdx.x * blockDim.x + threadIdx.x;
    if (i < NN) {
        int r = g_rp[i] + g_boff[i >> 8];
        g_rp[i] = r;
        g_cursor[i] = r;
        if (i == 0) g_rp[NN] = EE;
    }
}
__global__ void k_scatter(const int* __restrict__ src, const int* __restrict__ dst) {
    int e = blockIdx.x * blockDim.x + threadIdx.x;
    if (e < EE) {
        int p = atomicAdd(&g_cursor[dst[e]], 1);
        g_csrc[p] = src[e];
    }
}

// ---------------- conv0 max aggregation ----------------
__global__ void k_agg0(const float* __restrict__ x) {
    int wi = (blockIdx.x * blockDim.x + threadIdx.x) >> 5;
    if (wi >= NN) return;
    int lane = threadIdx.x & 31;
    int beg = g_rp[wi], end = g_rp[wi + 1];
    float m0 = -3.4e38f, m1 = -3.4e38f;
    for (int e = beg; e < end; e++) {
        int s = g_csrc[e];
        m0 = fmaxf(m0, x[s * FEAT + lane]);
        m1 = fmaxf(m1, x[s * FEAT + 32 + lane]);
    }
    if (beg == end) { m0 = 0.f; m1 = 0.f; }
    g_aggf[wi * FEAT + lane] = m0;
    g_aggf[wi * FEAT + 32 + lane] = m1;
}

// ---------------- conv0 GEMM + fused BN partial stats ----------------
// 256 thr, 32 nodes/block, tile 4x4. Epilogue accumulates per-feature sum/sumsq.
__global__ void k_conv0(const float* __restrict__ x, const float* __restrict__ wrel,
                        const float* __restrict__ wroot, const float* __restrict__ b0) {
    __shared__ float sW[64 * 132];
    __shared__ float sIn[64 * 36];
    int tx = threadIdx.x;
    int og = tx & 31;
    int ng = tx >> 5;
    int nbase = blockIdx.x * 32;

    float acc[4][4];
#pragma unroll
    for (int p = 0; p < 4; p++)
#pragma unroll
        for (int q = 0; q < 4; q++) acc[p][q] = 0.f;

    for (int c = 0; c < 2; c++) {
        const float* W = c ? wroot : wrel;
        const float* In = c ? x : g_aggf;
#pragma unroll
        for (int r = 0; r < 32; r++) {
            int lin = r * 256 + tx;
            int j = lin >> 6, k = lin & 63;
            sW[k * 132 + j] = W[j * 64 + k];
        }
#pragma unroll
        for (int r = 0; r < 8; r++) {
            int lin = r * 256 + tx;
            int n = lin >> 6, k = lin & 63;
            sIn[k * 36 + n] = In[(nbase + n) * 64 + k];
        }
        __syncthreads();
#pragma unroll 16
        for (int k = 0; k < 64; k++) {
            float4 wv = *(const float4*)&sW[k * 132 + og * 4];
            float4 iv = *(const float4*)&sIn[k * 36 + ng * 4];
            acc[0][0] += iv.x * wv.x; acc[0][1] += iv.x * wv.y; acc[0][2] += iv.x * wv.z; acc[0][3] += iv.x * wv.w;
            acc[1][0] += iv.y * wv.x; acc[1][1] += iv.y * wv.y; acc[1][2] += iv.y * wv.z; acc[1][3] += iv.y * wv.w;
            acc[2][0] += iv.z * wv.x; acc[2][1] += iv.z * wv.y; acc[2][2] += iv.z * wv.z; acc[2][3] += iv.z * wv.w;
            acc[3][0] += iv.w * wv.x; acc[3][1] += iv.w * wv.y; acc[3][2] += iv.w * wv.z; acc[3][3] += iv.w * wv.w;
        }
        __syncthreads();
    }
    int j0 = og * 4;
    float4 bb = *(const float4*)&b0[j0];
    float s[4] = {0, 0, 0, 0}, ss[4] = {0, 0, 0, 0};
#pragma unroll
    for (int p = 0; p < 4; p++) {
        int node = nbase + ng * 4 + p;
        float v0 = lrelu(acc[p][0] + bb.x);
        float v1 = lrelu(acc[p][1] + bb.y);
        float v2 = lrelu(acc[p][2] + bb.z);
        float v3 = lrelu(acc[p][3] + bb.w);
        float4 o = {v0, v1, v2, v3};
        *(float4*)&g_buf[node * EMB + j0] = o;
        s[0] += v0; ss[0] += v0 * v0;
        s[1] += v1; ss[1] += v1 * v1;
        s[2] += v2; ss[2] += v2 * v2;
        s[3] += v3; ss[3] += v3 * v3;
    }
    // reuse sW region for partial reduction: [feature 0..127][ng 0..7] float2
    float2* pr = (float2*)sW;
#pragma unroll
    for (int q = 0; q < 4; q++)
        pr[(j0 + q) * 8 + ng] = make_float2(s[q], ss[q]);
    __syncthreads();
    if (tx < 128) {
        float a = 0.f, a2 = 0.f;
#pragma unroll
        for (int w = 0; w < 8; w++) {
            float2 v = pr[tx * 8 + w];
            a += v.x; a2 += v.y;
        }
        g_part[blockIdx.x * EMB + tx] = a;
        g_part2[blockIdx.x * EMB + tx] = a2;
    }
}

// ---------------- reduce partials -> mean, inv-std ----------------
__global__ void k_statsR(int P) {
    int f = blockIdx.x, t = threadIdx.x;  // 128 blocks x 256 thr
    float s = 0.f, ss = 0.f;
    for (int p = t; p < P; p += 256) {
        s += g_part[p * EMB + f];
        ss += g_part2[p * EMB + f];
    }
    __shared__ float r1[256], r2[256];
    r1[t] = s; r2[t] = ss;
    __syncthreads();
    for (int o = 128; o > 0; o >>= 1) {
        if (t < o) { r1[t] += r1[t + o]; r2[t] += r2[t + o]; }
        __syncthreads();
    }
    if (t == 0) {
        float mean = r1[0] * (1.f / NN);
        float var = r2[0] * (1.f / NN) - mean * mean;
        g_meanvar[f] = mean;
        g_meanvar[EMB + f] = 1.f / sqrtf(var + 1e-5f);
    }
}

// ---------------- fused: BN-apply/update + pool scores + softmax + keep + compact ----------------
// grid = 256 graphs, 256 threads (8 warps). mode 0: cur = bn(buf). mode 1: cur = 0.5*cur+0.25*bn(masked buf)
__global__ void k_A(int mode, const float* __restrict__ gam, const float* __restrict__ bet,
                    const float* __restrict__ w4, float min_score) {
    int g = blockIdx.x, t = threadIdx.x;
    int w = t >> 5, lane = t & 31;
    __shared__ float sG[128], sBt[128], sMu[128], sRs[128];
    __shared__ float sW[4 * 128];
    __shared__ float sc[4][256];
    __shared__ float red[256];
    __shared__ int iarr[256];
    if (t < 128) {
        sG[t] = gam[t]; sBt[t] = bet[t];
        sMu[t] = g_meanvar[t]; sRs[t] = g_meanvar[EMB + t];
    }
    sW[t] = w4[t];
    sW[256 + t] = w4[256 + t];
    __syncthreads();

    int f0 = lane * 4;
    float4 gg = *(float4*)&sG[f0], bb = *(float4*)&sBt[f0];
    float4 mm = *(float4*)&sMu[f0], rr = *(float4*)&sRs[f0];
    float4 w0v = *(float4*)&sW[0 * 128 + f0];
    float4 w1v = *(float4*)&sW[1 * 128 + f0];
    float4 w2v = *(float4*)&sW[2 * 128 + f0];
    float4 w3v = *(float4*)&sW[3 * 128 + f0];

    for (int i = 0; i < 32; i++) {
        int gi = g * 256 + w * 32 + i;
        float4 v;
        if (mode == 0) {
            float4 b = *(const float4*)&g_buf[gi * EMB + f0];
            v.x = gg.x * (b.x - mm.x) * rr.x + bb.x;
            v.y = gg.y * (b.y - mm.y) * rr.y + bb.y;
            v.z = gg.z * (b.z - mm.z) * rr.z + bb.z;
            v.w = gg.w * (b.w - mm.w) * rr.w + bb.w;
        } else {
            float4 c = *(const float4*)&g_cur[gi * EMB + f0];
            unsigned mb = g_mask[gi];
            float4 b = {0.f, 0.f, 0.f, 0.f};
            if (mb) b = *(const float4*)&g_buf[gi * EMB + f0];
            float n0 = gg.x * (b.x - mm.x) * rr.x + bb.x;
            float n1 = gg.y * (b.y - mm.y) * rr.y + bb.y;
            float n2 = gg.z * (b.z - mm.z) * rr.z + bb.z;
            float n3 = gg.w * (b.w - mm.w) * rr.w + bb.w;
            v.x = 0.5f * c.x + 0.25f * n0;
            v.y = 0.5f * c.y + 0.25f * n1;
            v.z = 0.5f * c.z + 0.25f * n2;
            v.w = 0.5f * c.w + 0.25f * n3;
        }
        *(float4*)&g_cur[gi * EMB + f0] = v;
        float p0 = v.x * w0v.x + v.y * w0v.y + v.z * w0v.z + v.w * w0v.w;
        float p1 = v.x * w1v.x + v.y * w1v.y + v.z * w1v.z + v.w * w1v.w;
        float p2 = v.x * w2v.x + v.y * w2v.y + v.z * w2v.z + v.w * w2v.w;
        float p3 = v.x * w3v.x + v.y * w3v.y + v.z * w3v.z + v.w * w3v.w;
#pragma unroll
        for (int o = 16; o; o >>= 1) {
            p0 += __shfl_xor_sync(0xffffffffu, p0, o);
            p1 += __shfl_xor_sync(0xffffffffu, p1, o);
            p2 += __shfl_xor_sync(0xffffffffu, p2, o);
            p3 += __shfl_xor_sync(0xffffffffu, p3, o);
        }
        if (lane == 0) {
            int n = w * 32 + i;
            sc[0][n] = p0; sc[1][n] = p1; sc[2][n] = p2; sc[3][n] = p3;
        }
    }
    __syncthreads();

    // per-head softmax + keep (thread t owns node t)
    unsigned mb = 0;
    for (int h = 0; h < NHD; h++) {
        float vv = sc[h][t];
        red[t] = vv; __syncthreads();
        for (int o = 128; o > 0; o >>= 1) {
            if (t < o) red[t] = fmaxf(red[t], red[t + o]);
            __syncthreads();
        }
        float m = red[0]; __syncthreads();
        float e = expf(vv - m);
        red[t] = e; __syncthreads();
        for (int o = 128; o > 0; o >>= 1) {
            if (t < o) red[t] += red[t + o];
            __syncthreads();
        }
        float s = red[0]; __syncthreads();
        float sm = e / (s + 1e-16f);
        float smax = 1.0f / (s + 1e-16f);
        float thr = fminf(smax - 1e-7f, min_score);
        if (sm > thr) mb |= (1u << h);
        g_sm[h * NN + g * 256 + t] = sm;
    }
    g_mask[g * 256 + t] = (unsigned char)mb;

    // deterministic compaction of kept nodes
    int flag = mb ? 1 : 0;
    iarr[t] = flag; __syncthreads();
    for (int off = 1; off < 256; off <<= 1) {
        int xv = (t >= off) ? iarr[t - off] : 0;
        __syncthreads(); iarr[t] += xv; __syncthreads();
    }
    if (flag) g_klist[g * 256 + iarr[t] - 1] = t | ((int)mb << 8);
    if (t == 255) g_kcnt[g] = iarr[255];
}

// ---------------- block head conv on kept nodes + fused BN partials ----------------
// grid = 256 graphs, 128 threads; thread t produces feature t of each kept row
__global__ void k_head(const float* __restrict__ wrel, const float* __restrict__ wroot,
                       const float* __restrict__ bias) {
    int g = blockIdx.x, t = threadIdx.x;
    int cnt = g_kcnt[g];
    int h = t >> 5, j = t & 31;
    __shared__ float sCur[128];
    __shared__ float sAgg[NHD][128];
    float s_acc = 0.f, ss_acc = 0.f;
    for (int kk = 0; kk < cnt; kk++) {
        int pk = g_klist[g * 256 + kk];
        int i = g * 256 + (pk & 255);
        unsigned mb = (pk >> 8) & 15;
        sCur[t] = g_cur[i * EMB + t];
        int beg = g_rp[i], end = g_rp[i + 1];
#pragma unroll
        for (int hh = 0; hh < NHD; hh++) {
            if (!((mb >> hh) & 1)) continue;
            float m = -3.4e38f;
            bool any = false;
            for (int e = beg; e < end; e++) {
                int sidx = g_csrc[e];
                if ((g_mask[sidx] >> hh) & 1) {
                    m = fmaxf(m, g_cur[sidx * EMB + t] * g_sm[hh * NN + sidx]);
                    any = true;
                }
            }
            sAgg[hh][t] = any ? m : 0.f;
        }
        __syncthreads();
        float v = 0.f;
        if ((mb >> h) & 1) {
            float smv = g_sm[h * NN + i];
            float accv = bias[h * OUTD + j];
            const float* wr = &wrel[(h * OUTD + j) * EMB];
            const float* wo = &wroot[(h * OUTD + j) * EMB];
#pragma unroll 16
            for (int k = 0; k < EMB; k++)
                accv += wr[k] * sAgg[h][k] + wo[k] * (sCur[k] * smv);
            v = lrelu(accv);
        }
        g_buf[i * EMB + t] = v;
        s_acc += v; ss_acc += v * v;
        __syncthreads();
    }
    g_part[g * EMB + t] = s_acc;
    g_part2[g * EMB + t] = ss_acc;
}

// ---------------- fused classifier: gate MLP + attention softmax + pool + MLP + log_softmax ----------------
// grid = 256 graphs, 128 threads
__global__ void k_cls(const float* __restrict__ gW1, const float* __restrict__ gb1,
                      const float* __restrict__ gW2, const float* __restrict__ gb2,
                      const float* __restrict__ fW1, const float* __restrict__ fb1,
                      const float* __restrict__ fW2, const float* __restrict__ fb2,
                      float* __restrict__ out) {
    int g = blockIdx.x, t = threadIdx.x;
    __shared__ float gate_s[NHD][256];
    __shared__ float red[128];
    __shared__ float sCur[128];
    __shared__ float sPool[128];
    __shared__ float sLog[NHD];
    for (int idx = t; idx < NHD * 256; idx += 128)
        ((float*)gate_s)[idx] = NEG_INF;
    int cnt = g_kcnt[g];
    __syncthreads();

    // gate values at kept nodes
    for (int kk = 0; kk < cnt; kk++) {
        int pk = g_klist[g * 256 + kk];
        int n = pk & 255;
        unsigned mb = (pk >> 8) & 15;
        int i = g * 256 + n;
        sCur[t] = g_cur[i * EMB + t];
        __syncthreads();
        for (int c = 0; c < NHD; c++) {
            if (!((mb >> c) & 1)) continue;
            float smv = g_sm[c * NN + i];
            float accv = gb1[c * EMB + t];
            const float* wp = &gW1[(c * EMB + t) * EMB];
#pragma unroll 16
            for (int k = 0; k < EMB; k++) accv += wp[k] * (sCur[k] * smv);
            accv = lrelu(accv);
            red[t] = accv * gW2[c * EMB + t];
            __syncthreads();
            for (int o = 64; o > 0; o >>= 1) {
                if (t < o) red[t] += red[t + o];
                __syncthreads();
            }
            if (t == 0) gate_s[c][n] = red[0] + gb2[c];
            __syncthreads();
        }
        __syncthreads();
    }

    // per-head softmax over kept nodes + pooled + final MLP
    for (int c = 0; c < NHD; c++) {
        red[t] = fmaxf(gate_s[c][t], gate_s[c][t + 128]);
        __syncthreads();
        for (int o = 64; o > 0; o >>= 1) {
            if (t < o) red[t] = fmaxf(red[t], red[t + o]);
            __syncthreads();
        }
        float m = red[0]; __syncthreads();
        float e0 = expf(gate_s[c][t] - m);      // exp(-inf - m) = 0
        float e1 = expf(gate_s[c][t + 128] - m);
        red[t] = e0 + e1;
        __syncthreads();
        for (int o = 64; o > 0; o >>= 1) {
            if (t < o) red[t] += red[t + o];
            __syncthreads();
        }
        float s = red[0] + 1e-16f; __syncthreads();

        float pool = 0.f;
        for (int kk = 0; kk < cnt; kk++) {
            int pk = g_klist[g * 256 + kk];
            int n = pk & 255;
            unsigned mb = (pk >> 8) & 15;
            if (!((mb >> c) & 1)) continue;
            int i = g * 256 + n;
            float a = expf(gate_s[c][n] - m) / s;
            pool += a * g_sm[c * NN + i] * g_cur[i * EMB + t];
        }
        sPool[t] = pool;
        __syncthreads();
        float accv = fb1[c * EMB + t];
        const float* wp = &fW1[(c * EMB + t) * EMB];
#pragma unroll 16
        for (int k = 0; k < EMB; k++) accv += wp[k] * sPool[k];
        accv = lrelu(accv);
        red[t] = accv * fW2[c * EMB + t];
        __syncthreads();
        for (int o = 64; o > 0; o >>= 1) {
            if (t < o) red[t] += red[t + o];
            __syncthreads();
        }
        if (t == 0) sLog[c] = red[0] + fb2[c];
        __syncthreads();
    }

    if (t < NHD) {
        float m = fmaxf(fmaxf(sLog[0], sLog[1]), fmaxf(sLog[2], sLog[3]));
        float s = expf(sLog[0] - m) + expf(sLog[1] - m) + expf(sLog[2] - m) + expf(sLog[3] - m);
        out[g * NHD + t] = sLog[t] - m - logf(s);
    }
}

// ---------------- launch ----------------
extern "C" void kernel_launch(void* const* d_in, const int* in_sizes, int n_in,
                              void* d_out, int out_size) {
    const float* x       = (const float*)d_in[0];
    const int*   ei      = (const int*)d_in[1];
    const int*   src     = ei;
    const int*   dst     = ei + EE;
    const float* Wrel0   = (const float*)d_in[3];
    const float* Wroot0  = (const float*)d_in[4];
    const float* b0      = (const float*)d_in[5];
    const float* bn0g    = (const float*)d_in[6];
    const float* bn0b    = (const float*)d_in[7];
    const float* blk_pw  = (const float*)d_in[8];
    const float* blk_Wr  = (const float*)d_in[9];
    const float* blk_Wo  = (const float*)d_in[10];
    const float* blk_bb  = (const float*)d_in[11];
    const float* blk_bng = (const float*)d_in[12];
    const float* blk_bnb = (const float*)d_in[13];
    const float* cls_pw  = (const float*)d_in[14];
    const float* gW1     = (const float*)d_in[15];
    const float* gb1     = (const float*)d_in[16];
    const float* gW2     = (const float*)d_in[17];
    const float* gb2     = (const float*)d_in[18];
    const float* fW1     = (const float*)d_in[19];
    const float* fb1     = (const float*)d_in[20];
    const float* fW2     = (const float*)d_in[21];
    const float* fb2     = (const float*)d_in[22];
    float* out = (float*)d_out;

    // CSR by dst
    k_zero_deg<<<256, 256>>>();
    k_hist<<<EE / 256, 256>>>(dst);
    k_scan1<<<256, 256>>>();
    k_scan2<<<1, 256>>>();
    k_scan3<<<256, 256>>>();
    k_scatter<<<EE / 256, 256>>>(src, dst);

    // conv0 (+ fused stats partials) -> statsR -> A0 (bn0 + pool0 scores/keep)
    k_agg0<<<NN / 8, 256>>>(x);
    k_conv0<<<NN / 32, 256>>>(x, Wrel0, Wroot0, b0);
    k_statsR<<<EMB, 256>>>(NN / 32);
    k_A<<<BBG, 256>>>(0, bn0g, bn0b, blk_pw + 0 * NHD * EMB, 0.7f);

    // block 0
    k_head<<<BBG, 128>>>(blk_Wr, blk_Wo, blk_bb);
    k_statsR<<<EMB, 256>>>(BBG);
    k_A<<<BBG, 256>>>(1, blk_bng, blk_bnb, blk_pw + 1 * NHD * EMB, 0.7f);

    // block 1
    k_head<<<BBG, 128>>>(blk_Wr + NHD * OUTD * EMB, blk_Wo + NHD * OUTD * EMB, blk_bb + NHD * OUTD);
    k_statsR<<<EMB, 256>>>(BBG);
    k_A<<<BBG, 256>>>(1, blk_bng + EMB, blk_bnb + EMB, cls_pw, 0.8f);

    // classifier heads (gate + attention + pool + MLP + log_softmax)
    k_cls<<<BBG, 128>>>(gW1, gb1, gW2, gb2, fW1, fb1, fW2, fb2, out);
}